// round 10
// baseline (speedup 1.0000x reference)
#include <cuda_runtime.h>
#include <cstdint>

#define Lq     8192
#define Eq     256
#define NCOL   2048      // 2 dirs * 4*HD
#define Tq     34
#define STARTq 32
#define CH     32        // CRF chunk length
#define NCH    256       // number of CRF chunks (Lq / CH)

// ---------------- scratch (static device globals; no runtime allocation) ----
__device__ float g_gates[Lq * NCOL];   // 64 MB: precomputed x@Wih^T + b, both dirs
__device__ float g_h[Lq * 512];        // 16 MB: [hf | hb]
__device__ float g_feats[Lq * Tq];
__device__ float g_la[Lq * Tq];
__device__ float g_lb[Lq * Tq];
// CRF parallel-scan scratch
__device__ float  g_M [2][NCH][Tq * Tq];  // chunk transfer matrices (exp domain, raw)
__device__ double g_Ms[2][NCH];           // log-scale of each chunk matrix
__device__ float  g_bv[2][NCH][Tq];       // boundary vectors entering each chunk (raw exp)
__device__ double g_bs[2][NCH];           // log-scale of boundary vectors

// ============================================================================
// Phase A: embedding gather + input projection GEMM (unchanged, passing)
// ============================================================================
__global__ void xproj_kernel(const int* __restrict__ words,
                             const float* __restrict__ embed,
                             const float* __restrict__ Wf, const float* __restrict__ bf,
                             const float* __restrict__ Wb, const float* __restrict__ bb)
{
    __shared__ float As[32][64];
    __shared__ float Bs[32][64];
    __shared__ int   sw[64];

    const int tid = threadIdx.x;                 // 256 threads
    const int bn = blockIdx.x, bm = blockIdx.y;  // grid (32, 128)
    const int tx = tid & 15, ty = tid >> 4;      // 16x16

    if (tid < 64) sw[tid] = words[bm * 64 + tid];
    __syncthreads();

    float acc[4][4];
    #pragma unroll
    for (int i = 0; i < 4; i++)
        #pragma unroll
        for (int j = 0; j < 4; j++) acc[i][j] = 0.f;

    for (int k0 = 0; k0 < Eq; k0 += 32) {
        #pragma unroll
        for (int p = 0; p < 8; p++) {
            int lin = p * 256 + tid;
            int m = lin >> 5, kk = lin & 31;
            As[kk][m] = embed[(size_t)sw[m] * Eq + (k0 + kk)];
        }
        #pragma unroll
        for (int p = 0; p < 8; p++) {
            int lin = p * 256 + tid;
            int n = lin >> 5, kk = lin & 31;
            int col = bn * 64 + n;
            const float* W = (col < 1024) ? Wf : Wb;
            int row = (col < 1024) ? col : col - 1024;
            Bs[kk][n] = W[row * Eq + (k0 + kk)];
        }
        __syncthreads();
        #pragma unroll
        for (int kk = 0; kk < 32; kk++) {
            float4 av = *(const float4*)&As[kk][ty * 4];
            float4 bv = *(const float4*)&Bs[kk][tx * 4];
            float a[4] = {av.x, av.y, av.z, av.w};
            float b[4] = {bv.x, bv.y, bv.z, bv.w};
            #pragma unroll
            for (int i = 0; i < 4; i++)
                #pragma unroll
                for (int j = 0; j < 4; j++)
                    acc[i][j] = fmaf(a[i], b[j], acc[i][j]);
        }
        __syncthreads();
    }

    #pragma unroll
    for (int i = 0; i < 4; i++) {
        int t = bm * 64 + ty * 4 + i;
        #pragma unroll
        for (int j = 0; j < 4; j++) {
            int col = bn * 64 + tx * 4 + j;
            float bias = (col < 1024) ? bf[col] : bb[col - 1024];
            g_gates[(size_t)t * NCOL + col] = acc[i][j] + bias;
        }
    }
}

// ============================================================================
// Phase B: recurrent BiLSTM. 2 clusters of 8 CTAs, 512 threads/CTA.
// Sync per step: scatter st.shared::cluster (data) -> __syncthreads ->
// fence.acq_rel.cluster + 8 remote mbarrier arrives (warp-0 lanes, count=8
// per dest mbar) -> consumer HW-sleep try_wait.acquire.cluster.
// Double-buffered h; NO barrier.cluster in the loop.
// ============================================================================
__global__ void __cluster_dims__(8, 1, 1) __launch_bounds__(512, 1)
lstm_kernel(const float* __restrict__ Whh_f, const float* __restrict__ Whh_b)
{
    __shared__ __align__(16) float sh_h[2][256];
    __shared__ __align__(8)  unsigned long long sh_mbar[2];

    const int tid = threadIdx.x;
    unsigned rank; asm("mov.u32 %0, %%cluster_ctarank;" : "=r"(rank));
    const int dir = blockIdx.x >> 3;
    const int j   = tid >> 4;          // unit within CTA (0..31)
    const int g   = (tid >> 2) & 3;    // gate i,f,g,o
    const int c   = tid & 3;           // 64-col chunk
    const int u   = (int)rank * 32 + j;       // global hidden unit (0..255)
    const int row = g * 256 + u;              // Whh row
    const float* Whh = dir ? Whh_b : Whh_f;

    // weights: 64 floats packed as 32 f32x2 pairs in registers
    unsigned long long w2[32];
    {
        const ulonglong2* wp = (const ulonglong2*)(Whh + (size_t)row * 256 + c * 64);
        #pragma unroll
        for (int q = 0; q < 16; q++) { ulonglong2 t = wp[q]; w2[2*q] = t.x; w2[2*q+1] = t.y; }
    }

    const uint32_t hbase = (uint32_t)__cvta_generic_to_shared(&sh_h[0][0]);
    const uint32_t mbase = (uint32_t)__cvta_generic_to_shared(&sh_mbar[0]);

    if (tid < 256) sh_h[0][tid] = 0.f;
    if (tid == 0) {
        asm volatile("mbarrier.init.shared::cta.b64 [%0], 8;" :: "r"(mbase)     : "memory");
        asm volatile("mbarrier.init.shared::cta.b64 [%0], 8;" :: "r"(mbase + 8) : "memory");
        asm volatile("fence.mbarrier_init.release.cluster;" ::: "memory");
    }
    __syncthreads();
    asm volatile("barrier.cluster.arrive.aligned;" ::: "memory");
    asm volatile("barrier.cluster.wait.aligned;"   ::: "memory");

    // remote data addresses of slot u in peer (dst = tid&7), both parities
    uint32_t d0, d1;
    {
        int dst = tid & 7;
        uint32_t a0 = hbase + (uint32_t)u * 4u;
        uint32_t a1 = hbase + (uint32_t)(256 + u) * 4u;
        asm("mapa.shared::cluster.u32 %0, %1, %2;" : "=r"(d0) : "r"(a0), "r"(dst));
        asm("mapa.shared::cluster.u32 %0, %1, %2;" : "=r"(d1) : "r"(a1), "r"(dst));
    }
    // remote mbar addresses (warp-0 lanes 0..7 only)
    uint32_t rm0 = 0, rm1 = 0;
    if (tid < 8) {
        asm("mapa.shared::cluster.u32 %0, %1, %2;" : "=r"(rm0) : "r"(mbase),      "r"(tid));
        asm("mapa.shared::cluster.u32 %0, %1, %2;" : "=r"(rm1) : "r"(mbase + 8u), "r"(tid));
    }

    const long xstep = dir ? -(long)NCOL : (long)NCOL;
    const float* px  = g_gates + ((long)dir * 1024 + (long)g * 256 + u)
                     + (dir ? (long)(Lq - 1) * NCOL : 0);
    float*       ph  = g_h + (dir ? (long)(Lq - 1) * 512 : 0) + dir * 256 + u;
    const long hstep = dir ? -512L : 512L;

    float xc = *px;
    float cstate = 0.f;
    unsigned phw = 0;                  // phase bits: bit0 = mbar0, bit1 = mbar1

    for (int it = 0; it < Lq; ++it) {
        const int buf = it & 1, nb = buf ^ 1;

        // issue next step's gate prefetch early (independent of the wait)
        float xn = (it + 1 < Lq) ? px[xstep] : 0.f;

        if (it) {
            // wait for all 8 CTAs' h slices for buffer buf (armed last step)
            uint32_t mb = mbase + ((uint32_t)buf << 3);
            unsigned p = (phw >> buf) & 1u;
            asm volatile("{\n\t.reg .pred P;\n\t"
                "WAIT%=:\n\t"
                "mbarrier.try_wait.parity.acquire.cluster.shared::cta.b64 P, [%0], %1, 0x989680;\n\t"
                "@P bra DONE%=;\n\t"
                "bra WAIT%=;\n\t"
                "DONE%=:\n\t}" :: "r"(mb), "r"(p) : "memory");
            phw ^= 1u << buf;
        }

        // packed matvec: 64 MACs = 32 FFMA.f32x2, 4 independent accumulators
        unsigned long long acc0 = 0ull, acc1 = 0ull, acc2 = 0ull, acc3 = 0ull;
        uint32_t ha = hbase + (uint32_t)(buf * 1024 + c * 256);
        #pragma unroll
        for (int q = 0; q < 8; q++) {
            unsigned long long h0, h1, h2, h3;
            asm("ld.shared.v2.u64 {%0,%1}, [%2];" : "=l"(h0), "=l"(h1) : "r"(ha + q * 32));
            asm("ld.shared.v2.u64 {%0,%1}, [%2];" : "=l"(h2), "=l"(h3) : "r"(ha + q * 32 + 16));
            asm("fma.rn.f32x2 %0, %1, %2, %0;" : "+l"(acc0) : "l"(w2[4*q + 0]), "l"(h0));
            asm("fma.rn.f32x2 %0, %1, %2, %0;" : "+l"(acc1) : "l"(w2[4*q + 1]), "l"(h1));
            asm("fma.rn.f32x2 %0, %1, %2, %0;" : "+l"(acc2) : "l"(w2[4*q + 2]), "l"(h2));
            asm("fma.rn.f32x2 %0, %1, %2, %0;" : "+l"(acc3) : "l"(w2[4*q + 3]), "l"(h3));
        }
        float s;
        {
            float p0, p1, p2, p3, p4, p5, p6, p7;
            asm("mov.b64 {%0,%1}, %2;" : "=f"(p0), "=f"(p1) : "l"(acc0));
            asm("mov.b64 {%0,%1}, %2;" : "=f"(p2), "=f"(p3) : "l"(acc1));
            asm("mov.b64 {%0,%1}, %2;" : "=f"(p4), "=f"(p5) : "l"(acc2));
            asm("mov.b64 {%0,%1}, %2;" : "=f"(p6), "=f"(p7) : "l"(acc3));
            s = ((p0 + p1) + (p2 + p3)) + ((p4 + p5) + (p6 + p7));
        }
        // chunk reduce (4 threads, same warp)
        s += __shfl_xor_sync(0xffffffffu, s, 1);
        s += __shfl_xor_sync(0xffffffffu, s, 2);
        float gv = s + xc;
        xc = xn;

        // activation: tanh gate directly; sigmoid via 0.5*tanh(x/2)+0.5
        float targ = (g == 2) ? gv : 0.5f * gv;
        float th;  asm("tanh.approx.f32 %0, %1;" : "=f"(th) : "f"(targ));
        float av = (g == 2) ? th : fmaf(0.5f, th, 0.5f);

        // gather all 4 gates of my unit (xor4 flips gate bit0, xor8 flips bit1)
        float u1 = __shfl_xor_sync(0xffffffffu, av, 4);
        float u2 = __shfl_xor_sync(0xffffffffu, av, 8);
        float u3 = __shfl_xor_sync(0xffffffffu, u1, 8);

        float iv = (g == 0) ? av : (g == 1) ? u1 : (g == 2) ? u2 : u3;
        float fv = (g == 0) ? u1 : (g == 1) ? av : (g == 2) ? u3 : u2;
        float gg = (g == 0) ? u2 : (g == 1) ? u3 : (g == 2) ? av : u1;
        float ov = (g == 0) ? u3 : (g == 1) ? u2 : (g == 2) ? u1 : av;

        cstate = fmaf(fv, cstate, iv * gg);
        float cth; asm("tanh.approx.f32 %0, %1;" : "=f"(cth) : "f"(cstate));
        float hv = ov * cth;

        // scatter h: 8 lanes per unit each store hv to one peer CTA (incl self)
        if ((tid & 15) < 8) {
            uint32_t da = nb ? d1 : d0;
            asm volatile("st.shared::cluster.f32 [%0], %1;"
                         :: "r"(da), "f"(hv) : "memory");
        } else if ((tid & 15) == 8) {
            *ph = hv;
        }
        ph += hstep;
        px += xstep;

        __syncthreads();                    // all stores issued CTA-wide
        if (tid < 8) {
            asm volatile("fence.acq_rel.cluster;" ::: "memory");
            uint32_t ra = nb ? rm1 : rm0;
            asm volatile("mbarrier.arrive.release.cluster.shared::cluster.b64 _, [%0];"
                         :: "r"(ra) : "memory");
        }
    }
    asm volatile("barrier.cluster.arrive.aligned;" ::: "memory");
    asm volatile("barrier.cluster.wait.aligned;"   ::: "memory");
}

// ============================================================================
// Phase C: feats[t][j] = h[t] . W_out[j] + b_out[j]   (unchanged, passing)
// ============================================================================
__global__ void feats_kernel(const float* __restrict__ Wout,
                             const float* __restrict__ bout)
{
    __shared__ float sh[4][512];
    const int tid = threadIdx.x;
    const int t0 = blockIdx.x * 4;
    #pragma unroll
    for (int p = 0; p < 8; p++) {
        int lin = p * 256 + tid;
        int r = lin >> 9, k = lin & 511;
        sh[r][k] = g_h[(long)(t0 + r) * 512 + k];
    }
    __syncthreads();
    const int tt = tid >> 6, j = tid & 63;
    if (j < Tq) {
        const float* wp = Wout + (size_t)j * 512;
        float s0 = 0.f, s1 = 0.f;
        #pragma unroll 8
        for (int k = 0; k < 512; k += 2) {
            s0 = fmaf(sh[tt][k],     __ldg(wp + k),     s0);
            s1 = fmaf(sh[tt][k + 1], __ldg(wp + k + 1), s1);
        }
        g_feats[(long)(t0 + tt) * Tq + j] = s0 + s1 + bout[j];
    }
}

// ============================================================================
// Phase D1: per-chunk transfer matrices (exp domain, per-step rescale).
// grid (NCH, 2). block 578: thread owns (j0=jp,i) and (j1=jp+17,i).
// ============================================================================
__global__ void __launch_bounds__(578, 1) crf_chunk_kernel(const float* __restrict__ trans)
{
    __shared__ float sA[2][Tq * Tq];
    __shared__ float sEF[CH][Tq];

    const int dir = blockIdx.y, cch = blockIdx.x;
    const int tid = threadIdx.x;
    const int i  = tid % Tq;
    const int jp = tid / Tq;           // 0..16
    const int j0 = jp, j1 = jp + 17;

    // stage exp(feat) for this chunk
    for (int p = tid; p < CH * Tq; p += 578)
        sEF[p / Tq][p % Tq] = __expf(g_feats[(long)(cch * CH + p / Tq) * Tq + (p % Tq)]);

    // exp(trans) rows (fwd) or columns (bwd) in registers
    float er0[Tq], er1[Tq];
    #pragma unroll
    for (int k = 0; k < Tq; k++) {
        if (dir == 0) { er0[k] = __expf(trans[j0 * Tq + k]); er1[k] = __expf(trans[j1 * Tq + k]); }
        else          { er0[k] = __expf(trans[k * Tq + j0]); er1[k] = __expf(trans[k * Tq + j1]); }
    }

    sA[0][j0 * Tq + i] = (j0 == i) ? 1.f : 0.f;
    sA[0][j1 * Tq + i] = (j1 == i) ? 1.f : 0.f;
    __syncthreads();

    double S = 0.0;
    #pragma unroll 1
    for (int st = 0; st < CH; ++st) {
        const int rb = st & 1, wb = rb ^ 1;
        const int t  = dir ? (CH - 1 - st) : st;   // local feat index
        float a00 = sA[rb][0];
        float r = __frcp_rn(a00);
        float f0 = 0.f, f1 = 0.f;
        if (dir == 0) {
            #pragma unroll
            for (int k = 0; k < Tq; k++) {
                float a = sA[rb][k * Tq + i];
                f0 = fmaf(er0[k], a, f0);
                f1 = fmaf(er1[k], a, f1);
            }
            f0 *= sEF[t][j0];
            f1 *= sEF[t][j1];
        } else {
            #pragma unroll
            for (int k = 0; k < Tq; k++) {
                float a = sA[rb][k * Tq + i] * sEF[t][k];
                f0 = fmaf(er0[k], a, f0);
                f1 = fmaf(er1[k], a, f1);
            }
        }
        S += (double)__logf(a00);
        sA[wb][j0 * Tq + i] = f0 * r;
        sA[wb][j1 * Tq + i] = f1 * r;
        __syncthreads();
    }
    // CH even -> final matrix sits in buffer 0
    g_M[dir][cch][j0 * Tq + i] = sA[0][j0 * Tq + i];
    g_M[dir][cch][j1 * Tq + i] = sA[0][j1 * Tq + i];
    if (tid == 0) g_Ms[dir][cch] = S;
}

// ============================================================================
// Phase D2: sequential compose across chunks (grid 2, block 64).
// ============================================================================
__global__ void crf_compose_kernel(const float* __restrict__ trans)
{
    __shared__ float sv[Tq];
    __shared__ float sd[Tq];
    const int dir = blockIdx.x;
    const int j = threadIdx.x;         // 64, j<34 active
    double V = 0.0;

    if (j < Tq) {
        if (dir == 0) sv[j] = (j == STARTq) ? 1.f : 0.f;   // ealpha_{-1}
        else {
            float s = 0.f;
            #pragma unroll
            for (int i = 0; i < Tq; i++) s += __expf(trans[i * Tq + j]);
            sv[j] = s;                                      // ebeta_{L-1}
        }
    }
    __syncthreads();

    for (int cc = 0; cc < NCH; ++cc) {
        const int cch = dir ? (NCH - 1 - cc) : cc;
        if (j < Tq) {
            g_bv[dir][cch][j] = sv[j];
            if (j == 0) g_bs[dir][cch] = V;
        }
        const float* M = g_M[dir][cch];
        float d = 0.f;
        if (j < Tq) {
            #pragma unroll
            for (int i = 0; i < Tq; i++) d = fmaf(M[j * Tq + i], sv[i], d);
            sd[j] = d;
        }
        __syncthreads();
        float s0 = sd[0];
        if (!(s0 > 0.f)) s0 = 1.f;
        if (j < Tq) sv[j] = sd[j] / s0;
        V += g_Ms[dir][cch] + (double)__logf(s0);
        __syncthreads();
    }
}

// ============================================================================
// Phase D3: chunk replay (grid (NCH,2), block 64): write g_la / g_lb.
// ============================================================================
__global__ void crf_replay_kernel(const float* __restrict__ trans)
{
    __shared__ float sv[2][Tq];
    __shared__ float sF [CH][Tq];
    __shared__ float sEF[CH][Tq];
    const int dir = blockIdx.y, cch = blockIdx.x;
    const int j = threadIdx.x;         // 64, j<34 active

    for (int p = j; p < CH * Tq; p += 64) {
        float f = g_feats[(long)(cch * CH + p / Tq) * Tq + (p % Tq)];
        sF [p / Tq][p % Tq] = f;
        sEF[p / Tq][p % Tq] = __expf(f);
    }
    float er[Tq];
    if (j < Tq) {
        #pragma unroll
        for (int i = 0; i < Tq; i++)
            er[i] = (dir == 0) ? __expf(trans[j * Tq + i]) : __expf(trans[i * Tq + j]);
    }
    double V = g_bs[dir][cch];
    if (j < Tq) sv[0][j] = g_bv[dir][cch][j];
    __syncthreads();

    if (dir == 0) {
        // forward: entering v = ealpha_{c*CH-1}; outputs t = c*CH .. c*CH+CH-1
        #pragma unroll 1
        for (int st = 0; st < CH; ++st) {
            const int rb = st & 1, wb = rb ^ 1;
            const long t = (long)cch * CH + st;
            float s0 = sv[rb][0];
            if (!(s0 > 0.f)) s0 = 1.f;
            if (j < Tq) {
                float d = 0.f;
                #pragma unroll
                for (int i = 0; i < Tq; i++) d = fmaf(er[i], sv[rb][i], d);
                g_la[t * Tq + j] = (float)((double)__logf(d) + V + (double)sF[st][j]);
                sv[wb][j] = __fdividef(d * sEF[st][j], s0);
            }
            V += (double)__logf(s0);
            __syncthreads();
        }
    } else {
        // backward: entering v = ebeta_{c*CH+CH-1}; outputs descending
        const long thi = (long)cch * CH + CH - 1;
        if (j < Tq) g_lb[thi * Tq + j] = (float)((double)__logf(sv[0][j]) + V);
        #pragma unroll 1
        for (int st = 0; st < CH - 1; ++st) {
            const int rb = st & 1, wb = rb ^ 1;
            const long t = thi - 1 - st;
            const int tf = (int)(t + 1 - (long)cch * CH);  // local index of feat_{t+1}
            float s0 = sv[rb][0];
            if (!(s0 > 0.f)) s0 = 1.f;
            if (j < Tq) {
                float d = 0.f;
                #pragma unroll
                for (int i = 0; i < Tq; i++)
                    d = fmaf(er[i] * sEF[tf][i], sv[rb][i], d);
                g_lb[t * Tq + j] = (float)((double)__logf(d) + V);
                sv[wb][j] = __fdividef(d, s0);
            }
            V += (double)__logf(s0);
            __syncthreads();
        }
    }
}

// ============================================================================
// Phase E: score = la + lb ; tags = argmax(score)  (first max wins)
// ============================================================================
__global__ void final_kernel(float* __restrict__ out, int out_size)
{
    int t = blockIdx.x * blockDim.x + threadIdx.x;
    if (t >= Lq) return;
    float best = -3.4e38f;
    int bi = 0;
    #pragma unroll
    for (int j = 0; j < Tq; j++) {
        float s = g_la[(long)t * Tq + j] + g_lb[(long)t * Tq + j];
        out[(long)t * Tq + j] = s;
        if (s > best) { best = s; bi = j; }
    }
    if (out_size >= Lq * Tq + Lq) out[(long)Lq * Tq + t] = (float)bi;
}

// ============================================================================
extern "C" void kernel_launch(void* const* d_in, const int* in_sizes, int n_in,
                              void* d_out, int out_size)
{
    const int*   words = (const int*)  d_in[0];
    const float* embed = (const float*)d_in[1];
    const float* Wih_f = (const float*)d_in[2];
    const float* Whh_f = (const float*)d_in[3];
    const float* b_f   = (const float*)d_in[4];
    const float* Wih_b = (const float*)d_in[5];
    const float* Whh_b = (const float*)d_in[6];
    const float* b_b   = (const float*)d_in[7];
    const float* W_out = (const float*)d_in[8];
    const float* b_out = (const float*)d_in[9];
    const float* trans = (const float*)d_in[10];
    float* out = (float*)d_out;

    xproj_kernel<<<dim3(32, 128), 256>>>(words, embed, Wih_f, b_f, Wih_b, b_b);
    lstm_kernel<<<16, 512>>>(Whh_f, Whh_b);
    feats_kernel<<<Lq / 4, 256>>>(W_out, b_out);
    crf_chunk_kernel  <<<dim3(NCH, 2), 578>>>(trans);
    crf_compose_kernel<<<2, 64>>>(trans);
    crf_replay_kernel <<<dim3(NCH, 2), 64>>>(trans);
    final_kernel<<<(Lq + 127) / 128, 128>>>(out, out_size);
}

// round 11
// speedup vs baseline: 1.6731x; 1.6731x over previous
#include <cuda_runtime.h>
#include <cstdint>

#define Lq     8192
#define Eq     256
#define NCOL   2048      // 2 dirs * 4*HD
#define Tq     34
#define STARTq 32
#define CH     32        // CRF chunk length
#define NCH    256       // number of CRF chunks (Lq / CH)

// ---------------- scratch (static device globals; no runtime allocation) ----
__device__ float g_gates[Lq * NCOL];   // 64 MB: precomputed x@Wih^T + b, both dirs
__device__ float g_h[Lq * 512];        // 16 MB: [hf | hb]
__device__ float g_feats[Lq * Tq];
__device__ float g_la[Lq * Tq];
__device__ float g_lb[Lq * Tq];
// CRF parallel-scan scratch
__device__ float  g_M [2][NCH][Tq * Tq];  // chunk transfer matrices (exp domain, raw)
__device__ double g_Ms[2][NCH];           // log-scale of each chunk matrix
__device__ float  g_bv[2][NCH][Tq];       // boundary vectors entering each chunk (raw exp)
__device__ double g_bs[2][NCH];           // log-scale of boundary vectors

// ============================================================================
// Phase A: embedding gather + input projection GEMM (unchanged, passing)
// ============================================================================
__global__ void xproj_kernel(const int* __restrict__ words,
                             const float* __restrict__ embed,
                             const float* __restrict__ Wf, const float* __restrict__ bf,
                             const float* __restrict__ Wb, const float* __restrict__ bb)
{
    __shared__ float As[32][64];
    __shared__ float Bs[32][64];
    __shared__ int   sw[64];

    const int tid = threadIdx.x;                 // 256 threads
    const int bn = blockIdx.x, bm = blockIdx.y;  // grid (32, 128)
    const int tx = tid & 15, ty = tid >> 4;      // 16x16

    if (tid < 64) sw[tid] = words[bm * 64 + tid];
    __syncthreads();

    float acc[4][4];
    #pragma unroll
    for (int i = 0; i < 4; i++)
        #pragma unroll
        for (int j = 0; j < 4; j++) acc[i][j] = 0.f;

    for (int k0 = 0; k0 < Eq; k0 += 32) {
        #pragma unroll
        for (int p = 0; p < 8; p++) {
            int lin = p * 256 + tid;
            int m = lin >> 5, kk = lin & 31;
            As[kk][m] = embed[(size_t)sw[m] * Eq + (k0 + kk)];
        }
        #pragma unroll
        for (int p = 0; p < 8; p++) {
            int lin = p * 256 + tid;
            int n = lin >> 5, kk = lin & 31;
            int col = bn * 64 + n;
            const float* W = (col < 1024) ? Wf : Wb;
            int row = (col < 1024) ? col : col - 1024;
            Bs[kk][n] = W[row * Eq + (k0 + kk)];
        }
        __syncthreads();
        #pragma unroll
        for (int kk = 0; kk < 32; kk++) {
            float4 av = *(const float4*)&As[kk][ty * 4];
            float4 bv = *(const float4*)&Bs[kk][tx * 4];
            float a[4] = {av.x, av.y, av.z, av.w};
            float b[4] = {bv.x, bv.y, bv.z, bv.w};
            #pragma unroll
            for (int i = 0; i < 4; i++)
                #pragma unroll
                for (int j = 0; j < 4; j++)
                    acc[i][j] = fmaf(a[i], b[j], acc[i][j]);
        }
        __syncthreads();
    }

    #pragma unroll
    for (int i = 0; i < 4; i++) {
        int t = bm * 64 + ty * 4 + i;
        #pragma unroll
        for (int j = 0; j < 4; j++) {
            int col = bn * 64 + tx * 4 + j;
            float bias = (col < 1024) ? bf[col] : bb[col - 1024];
            g_gates[(size_t)t * NCOL + col] = acc[i][j] + bias;
        }
    }
}

// ============================================================================
// Phase B: recurrent BiLSTM. 2 clusters of 8 CTAs, 512 threads/CTA.
// Sync = barrier.cluster (best measured). NEW: coalesced h broadcast —
// unit leaders stage 32 h-values in smem; after one __syncthreads, warp w
// (w<8) ships the whole 128B slice to peer w as ONE lane-coalesced
// st.shared::cluster (8 clean packets/CTA instead of 256 scattered 4B).
// Warp 8 writes g_h history coalesced.
// ============================================================================
__global__ void __cluster_dims__(8, 1, 1) __launch_bounds__(512, 1)
lstm_kernel(const float* __restrict__ Whh_f, const float* __restrict__ Whh_b)
{
    __shared__ __align__(16) float sh_h[2][256];
    __shared__ __align__(16) float sh_stage[32];

    const int tid = threadIdx.x;
    unsigned rank; asm("mov.u32 %0, %%cluster_ctarank;" : "=r"(rank));
    const int dir = blockIdx.x >> 3;
    const int j   = tid >> 4;          // unit within CTA (0..31)
    const int g   = (tid >> 2) & 3;    // gate i,f,g,o
    const int c   = tid & 3;           // 64-col chunk
    const int u   = (int)rank * 32 + j;       // global hidden unit (0..255)
    const int row = g * 256 + u;              // Whh row
    const int w   = tid >> 5, lane = tid & 31;
    const float* Whh = dir ? Whh_b : Whh_f;

    // weights: 64 floats packed as 32 f32x2 pairs in registers
    unsigned long long w2[32];
    {
        const ulonglong2* wp = (const ulonglong2*)(Whh + (size_t)row * 256 + c * 64);
        #pragma unroll
        for (int q = 0; q < 16; q++) { ulonglong2 t = wp[q]; w2[2*q] = t.x; w2[2*q+1] = t.y; }
    }

    const uint32_t hbase = (uint32_t)__cvta_generic_to_shared(&sh_h[0][0]);

    if (tid < 256) sh_h[0][tid] = 0.f;
    __syncthreads();
    asm volatile("barrier.cluster.arrive.aligned;" ::: "memory");
    asm volatile("barrier.cluster.wait.aligned;"   ::: "memory");

    // broadcast addresses: warp w (<8) writes slot [rank*32+lane] in peer w
    uint32_t dpe0 = 0, dpe1 = 0;
    if (w < 8) {
        uint32_t a0 = hbase + (uint32_t)((int)rank * 32 + lane) * 4u;
        asm("mapa.shared::cluster.u32 %0, %1, %2;" : "=r"(dpe0) : "r"(a0),           "r"(w));
        asm("mapa.shared::cluster.u32 %0, %1, %2;" : "=r"(dpe1) : "r"(a0 + 1024u),   "r"(w));
    }

    const long xstep = dir ? -(long)NCOL : (long)NCOL;
    const float* px  = g_gates + ((long)dir * 1024 + (long)g * 256 + u)
                     + (dir ? (long)(Lq - 1) * NCOL : 0);
    // warp 8 writes the h history (32 contiguous floats)
    float* ph = g_h + (dir ? (long)(Lq - 1) * 512 : 0) + dir * 256 + (int)rank * 32 + lane;
    const long hstep = dir ? -512L : 512L;

    float xc = *px;
    float cstate = 0.f;

    for (int it = 0; it < Lq; ++it) {
        const int buf = it & 1, nb = buf ^ 1;

        // prefetch next step's input-projection value (full-step latency cover)
        float xn = (it + 1 < Lq) ? px[xstep] : 0.f;

        // packed matvec: 64 MACs = 32 FFMA.f32x2, 4 independent accumulators
        unsigned long long acc0 = 0ull, acc1 = 0ull, acc2 = 0ull, acc3 = 0ull;
        uint32_t ha = hbase + (uint32_t)(buf * 1024 + c * 256);
        #pragma unroll
        for (int q = 0; q < 8; q++) {
            unsigned long long h0, h1, h2, h3;
            asm("ld.shared.v2.u64 {%0,%1}, [%2];" : "=l"(h0), "=l"(h1) : "r"(ha + q * 32));
            asm("ld.shared.v2.u64 {%0,%1}, [%2];" : "=l"(h2), "=l"(h3) : "r"(ha + q * 32 + 16));
            asm("fma.rn.f32x2 %0, %1, %2, %0;" : "+l"(acc0) : "l"(w2[4*q + 0]), "l"(h0));
            asm("fma.rn.f32x2 %0, %1, %2, %0;" : "+l"(acc1) : "l"(w2[4*q + 1]), "l"(h1));
            asm("fma.rn.f32x2 %0, %1, %2, %0;" : "+l"(acc2) : "l"(w2[4*q + 2]), "l"(h2));
            asm("fma.rn.f32x2 %0, %1, %2, %0;" : "+l"(acc3) : "l"(w2[4*q + 3]), "l"(h3));
        }
        float s;
        {
            float p0, p1, p2, p3, p4, p5, p6, p7;
            asm("mov.b64 {%0,%1}, %2;" : "=f"(p0), "=f"(p1) : "l"(acc0));
            asm("mov.b64 {%0,%1}, %2;" : "=f"(p2), "=f"(p3) : "l"(acc1));
            asm("mov.b64 {%0,%1}, %2;" : "=f"(p4), "=f"(p5) : "l"(acc2));
            asm("mov.b64 {%0,%1}, %2;" : "=f"(p6), "=f"(p7) : "l"(acc3));
            s = ((p0 + p1) + (p2 + p3)) + ((p4 + p5) + (p6 + p7));
        }
        // chunk reduce (4 threads, same warp)
        s += __shfl_xor_sync(0xffffffffu, s, 1);
        s += __shfl_xor_sync(0xffffffffu, s, 2);
        float gv = s + xc;
        xc = xn;

        // activation: tanh gate directly; sigmoid via 0.5*tanh(x/2)+0.5
        float targ = (g == 2) ? gv : 0.5f * gv;
        float th;  asm("tanh.approx.f32 %0, %1;" : "=f"(th) : "f"(targ));
        float av = (g == 2) ? th : fmaf(0.5f, th, 0.5f);

        // gather all 4 gates of my unit — three INDEPENDENT butterflies
        float u1 = __shfl_xor_sync(0xffffffffu, av, 4);
        float u2 = __shfl_xor_sync(0xffffffffu, av, 8);
        float u3 = __shfl_xor_sync(0xffffffffu, av, 12);

        float iv = (g == 0) ? av : (g == 1) ? u1 : (g == 2) ? u2 : u3;
        float fv = (g == 0) ? u1 : (g == 1) ? av : (g == 2) ? u3 : u2;
        float gg = (g == 0) ? u2 : (g == 1) ? u3 : (g == 2) ? av : u1;
        float ov = (g == 0) ? u3 : (g == 1) ? u2 : (g == 2) ? u1 : av;

        cstate = fmaf(fv, cstate, iv * gg);
        float cth; asm("tanh.approx.f32 %0, %1;" : "=f"(cth) : "f"(cstate));
        float hv = ov * cth;

        // stage this CTA's 32 h-values locally (one writer per unit)
        if ((tid & 15) == 0) sh_stage[j] = hv;
        __syncthreads();

        // coalesced broadcast: warp w ships the 128B slice to peer w
        if (w < 8) {
            float v = sh_stage[lane];
            uint32_t da = nb ? dpe1 : dpe0;
            asm volatile("st.shared::cluster.f32 [%0], %1;"
                         :: "r"(da), "f"(v) : "memory");
        } else if (w == 8) {
            *ph = sh_stage[lane];     // h history, 128B coalesced
        }
        ph += hstep;
        px += xstep;

        asm volatile("barrier.cluster.arrive.aligned;" ::: "memory");
        asm volatile("barrier.cluster.wait.aligned;"   ::: "memory");
    }
}

// ============================================================================
// Phase C: feats[t][j] = h[t] . W_out[j] + b_out[j]   (unchanged, passing)
// ============================================================================
__global__ void feats_kernel(const float* __restrict__ Wout,
                             const float* __restrict__ bout)
{
    __shared__ float sh[4][512];
    const int tid = threadIdx.x;
    const int t0 = blockIdx.x * 4;
    #pragma unroll
    for (int p = 0; p < 8; p++) {
        int lin = p * 256 + tid;
        int r = lin >> 9, k = lin & 511;
        sh[r][k] = g_h[(long)(t0 + r) * 512 + k];
    }
    __syncthreads();
    const int tt = tid >> 6, j = tid & 63;
    if (j < Tq) {
        const float* wp = Wout + (size_t)j * 512;
        float s0 = 0.f, s1 = 0.f;
        #pragma unroll 8
        for (int k = 0; k < 512; k += 2) {
            s0 = fmaf(sh[tt][k],     __ldg(wp + k),     s0);
            s1 = fmaf(sh[tt][k + 1], __ldg(wp + k + 1), s1);
        }
        g_feats[(long)(t0 + tt) * Tq + j] = s0 + s1 + bout[j];
    }
}

// ============================================================================
// Phase D1: per-chunk transfer matrices (exp domain, per-step rescale).
// grid (NCH, 2). block 578: thread owns (j0=jp,i) and (j1=jp+17,i).
// ============================================================================
__global__ void __launch_bounds__(578, 1) crf_chunk_kernel(const float* __restrict__ trans)
{
    __shared__ float sA[2][Tq * Tq];
    __shared__ float sEF[CH][Tq];

    const int dir = blockIdx.y, cch = blockIdx.x;
    const int tid = threadIdx.x;
    const int i  = tid % Tq;
    const int jp = tid / Tq;           // 0..16
    const int j0 = jp, j1 = jp + 17;

    // stage exp(feat) for this chunk
    for (int p = tid; p < CH * Tq; p += 578)
        sEF[p / Tq][p % Tq] = __expf(g_feats[(long)(cch * CH + p / Tq) * Tq + (p % Tq)]);

    // exp(trans) rows (fwd) or columns (bwd) in registers
    float er0[Tq], er1[Tq];
    #pragma unroll
    for (int k = 0; k < Tq; k++) {
        if (dir == 0) { er0[k] = __expf(trans[j0 * Tq + k]); er1[k] = __expf(trans[j1 * Tq + k]); }
        else          { er0[k] = __expf(trans[k * Tq + j0]); er1[k] = __expf(trans[k * Tq + j1]); }
    }

    sA[0][j0 * Tq + i] = (j0 == i) ? 1.f : 0.f;
    sA[0][j1 * Tq + i] = (j1 == i) ? 1.f : 0.f;
    __syncthreads();

    double S = 0.0;
    #pragma unroll 1
    for (int st = 0; st < CH; ++st) {
        const int rb = st & 1, wb = rb ^ 1;
        const int t  = dir ? (CH - 1 - st) : st;   // local feat index
        float a00 = sA[rb][0];
        float r = __frcp_rn(a00);
        float f0 = 0.f, f1 = 0.f;
        if (dir == 0) {
            #pragma unroll
            for (int k = 0; k < Tq; k++) {
                float a = sA[rb][k * Tq + i];
                f0 = fmaf(er0[k], a, f0);
                f1 = fmaf(er1[k], a, f1);
            }
            f0 *= sEF[t][j0];
            f1 *= sEF[t][j1];
        } else {
            #pragma unroll
            for (int k = 0; k < Tq; k++) {
                float a = sA[rb][k * Tq + i] * sEF[t][k];
                f0 = fmaf(er0[k], a, f0);
                f1 = fmaf(er1[k], a, f1);
            }
        }
        S += (double)__logf(a00);
        sA[wb][j0 * Tq + i] = f0 * r;
        sA[wb][j1 * Tq + i] = f1 * r;
        __syncthreads();
    }
    // CH even -> final matrix sits in buffer 0
    g_M[dir][cch][j0 * Tq + i] = sA[0][j0 * Tq + i];
    g_M[dir][cch][j1 * Tq + i] = sA[0][j1 * Tq + i];
    if (tid == 0) g_Ms[dir][cch] = S;
}

// ============================================================================
// Phase D2: sequential compose across chunks (grid 2, block 64).
// ============================================================================
__global__ void crf_compose_kernel(const float* __restrict__ trans)
{
    __shared__ float sv[Tq];
    __shared__ float sd[Tq];
    const int dir = blockIdx.x;
    const int j = threadIdx.x;         // 64, j<34 active
    double V = 0.0;

    if (j < Tq) {
        if (dir == 0) sv[j] = (j == STARTq) ? 1.f : 0.f;   // ealpha_{-1}
        else {
            float s = 0.f;
            #pragma unroll
            for (int i = 0; i < Tq; i++) s += __expf(trans[i * Tq + j]);
            sv[j] = s;                                      // ebeta_{L-1}
        }
    }
    __syncthreads();

    for (int cc = 0; cc < NCH; ++cc) {
        const int cch = dir ? (NCH - 1 - cc) : cc;
        if (j < Tq) {
            g_bv[dir][cch][j] = sv[j];
            if (j == 0) g_bs[dir][cch] = V;
        }
        const float* M = g_M[dir][cch];
        float d = 0.f;
        if (j < Tq) {
            #pragma unroll
            for (int i = 0; i < Tq; i++) d = fmaf(M[j * Tq + i], sv[i], d);
            sd[j] = d;
        }
        __syncthreads();
        float s0 = sd[0];
        if (!(s0 > 0.f)) s0 = 1.f;
        if (j < Tq) sv[j] = sd[j] / s0;
        V += g_Ms[dir][cch] + (double)__logf(s0);
        __syncthreads();
    }
}

// ============================================================================
// Phase D3: chunk replay (grid (NCH,2), block 64): write g_la / g_lb.
// ============================================================================
__global__ void crf_replay_kernel(const float* __restrict__ trans)
{
    __shared__ float sv[2][Tq];
    __shared__ float sF [CH][Tq];
    __shared__ float sEF[CH][Tq];
    const int dir = blockIdx.y, cch = blockIdx.x;
    const int j = threadIdx.x;         // 64, j<34 active

    for (int p = j; p < CH * Tq; p += 64) {
        float f = g_feats[(long)(cch * CH + p / Tq) * Tq + (p % Tq)];
        sF [p / Tq][p % Tq] = f;
        sEF[p / Tq][p % Tq] = __expf(f);
    }
    float er[Tq];
    if (j < Tq) {
        #pragma unroll
        for (int i = 0; i < Tq; i++)
            er[i] = (dir == 0) ? __expf(trans[j * Tq + i]) : __expf(trans[i * Tq + j]);
    }
    double V = g_bs[dir][cch];
    if (j < Tq) sv[0][j] = g_bv[dir][cch][j];
    __syncthreads();

    if (dir == 0) {
        // forward: entering v = ealpha_{c*CH-1}; outputs t = c*CH .. c*CH+CH-1
        #pragma unroll 1
        for (int st = 0; st < CH; ++st) {
            const int rb = st & 1, wb = rb ^ 1;
            const long t = (long)cch * CH + st;
            float s0 = sv[rb][0];
            if (!(s0 > 0.f)) s0 = 1.f;
            if (j < Tq) {
                float d = 0.f;
                #pragma unroll
                for (int i = 0; i < Tq; i++) d = fmaf(er[i], sv[rb][i], d);
                g_la[t * Tq + j] = (float)((double)__logf(d) + V + (double)sF[st][j]);
                sv[wb][j] = __fdividef(d * sEF[st][j], s0);
            }
            V += (double)__logf(s0);
            __syncthreads();
        }
    } else {
        // backward: entering v = ebeta_{c*CH+CH-1}; outputs descending
        const long thi = (long)cch * CH + CH - 1;
        if (j < Tq) g_lb[thi * Tq + j] = (float)((double)__logf(sv[0][j]) + V);
        #pragma unroll 1
        for (int st = 0; st < CH - 1; ++st) {
            const int rb = st & 1, wb = rb ^ 1;
            const long t = thi - 1 - st;
            const int tf = (int)(t + 1 - (long)cch * CH);  // local index of feat_{t+1}
            float s0 = sv[rb][0];
            if (!(s0 > 0.f)) s0 = 1.f;
            if (j < Tq) {
                float d = 0.f;
                #pragma unroll
                for (int i = 0; i < Tq; i++)
                    d = fmaf(er[i] * sEF[tf][i], sv[rb][i], d);
                g_lb[t * Tq + j] = (float)((double)__logf(d) + V);
                sv[wb][j] = __fdividef(d, s0);
            }
            V += (double)__logf(s0);
            __syncthreads();
        }
    }
}

// ============================================================================
// Phase E: score = la + lb ; tags = argmax(score)  (first max wins)
// ============================================================================
__global__ void final_kernel(float* __restrict__ out, int out_size)
{
    int t = blockIdx.x * blockDim.x + threadIdx.x;
    if (t >= Lq) return;
    float best = -3.4e38f;
    int bi = 0;
    #pragma unroll
    for (int j = 0; j < Tq; j++) {
        float s = g_la[(long)t * Tq + j] + g_lb[(long)t * Tq + j];
        out[(long)t * Tq + j] = s;
        if (s > best) { best = s; bi = j; }
    }
    if (out_size >= Lq * Tq + Lq) out[(long)Lq * Tq + t] = (float)bi;
}

// ============================================================================
extern "C" void kernel_launch(void* const* d_in, const int* in_sizes, int n_in,
                              void* d_out, int out_size)
{
    const int*   words = (const int*)  d_in[0];
    const float* embed = (const float*)d_in[1];
    const float* Wih_f = (const float*)d_in[2];
    const float* Whh_f = (const float*)d_in[3];
    const float* b_f   = (const float*)d_in[4];
    const float* Wih_b = (const float*)d_in[5];
    const float* Whh_b = (const float*)d_in[6];
    const float* b_b   = (const float*)d_in[7];
    const float* W_out = (const float*)d_in[8];
    const float* b_out = (const float*)d_in[9];
    const float* trans = (const float*)d_in[10];
    float* out = (float*)d_out;

    xproj_kernel<<<dim3(32, 128), 256>>>(words, embed, Wih_f, b_f, Wih_b, b_b);
    lstm_kernel<<<16, 512>>>(Whh_f, Whh_b);
    feats_kernel<<<Lq / 4, 256>>>(W_out, b_out);
    crf_chunk_kernel  <<<dim3(NCH, 2), 578>>>(trans);
    crf_compose_kernel<<<2, 64>>>(trans);
    crf_replay_kernel <<<dim3(NCH, 2), 64>>>(trans);
    final_kernel<<<(Lq + 127) / 128, 128>>>(out, out_size);
}